// round 13
// baseline (speedup 1.0000x reference)
#include <cuda_runtime.h>
#include <cuda_bf16.h>
#include <float.h>
#include <cstdint>

// Problem constants (fixed by the dataset)
#define MAX_NODES 100000
#define MAX_TOTAL 1703936   // E + n upper bound
#define D_FEAT 32
#define D_HID 64
#define D_OUT 64
#define TILE_E 32           // edges per CTA iteration (2 warp-pairs x 16)

// Scratch: per-node precomputed terms.
// U[j] = x_j @ W1[:32] + pos_j @ W1[32:35] + b1   (N x 64)
// P[i] = pos_i @ W1[32:35]                        (N x 64)
__device__ float g_U[MAX_NODES * D_HID];
__device__ float g_P[MAX_NODES * D_HID];
__device__ int g_is64;
// Normalized edge list (int32, self-loops appended): size total = E + n.
__device__ int g_SRC[MAX_TOTAL];
__device__ int g_DST[MAX_TOTAL];

// ---------------------------------------------------------------------------
// PTX helpers (sm_80-era: ldmatrix + mma.sync — valid on plain sm_103 target)
// ---------------------------------------------------------------------------
__device__ __forceinline__ uint32_t smem_to_u32(const void* p) {
    uint32_t a;
    asm("{ .reg .u64 t; cvta.to.shared.u64 t, %1; cvt.u32.u64 %0, t; }"
        : "=r"(a) : "l"(p));
    return a;
}
__device__ __forceinline__ void ldm_x4(uint32_t* r, uint32_t addr) {
    asm volatile("ldmatrix.sync.aligned.m8n8.x4.shared.b16 {%0,%1,%2,%3}, [%4];"
                 : "=r"(r[0]), "=r"(r[1]), "=r"(r[2]), "=r"(r[3]) : "r"(addr));
}
__device__ __forceinline__ void ldm_x2(uint32_t& r0, uint32_t& r1, uint32_t addr) {
    asm volatile("ldmatrix.sync.aligned.m8n8.x2.shared.b16 {%0,%1}, [%2];"
                 : "=r"(r0), "=r"(r1) : "r"(addr));
}
__device__ __forceinline__ void mma_bf16(float* c, const uint32_t* a,
                                         uint32_t b0, uint32_t b1) {
    asm volatile(
        "mma.sync.aligned.m16n8k16.row.col.f32.bf16.bf16.f32 "
        "{%0,%1,%2,%3}, {%4,%5,%6,%7}, {%8,%9}, {%0,%1,%2,%3};"
        : "+f"(c[0]), "+f"(c[1]), "+f"(c[2]), "+f"(c[3])
        : "r"(a[0]), "r"(a[1]), "r"(a[2]), "r"(a[3]), "r"(b0), "r"(b1));
}
__device__ __forceinline__ uint32_t pack_hi(float a, float b) {
    return __byte_perm(__float_as_uint(a), __float_as_uint(b), 0x7632);
}
__device__ __forceinline__ float resid(float x) {
    return x - __uint_as_float(__float_as_uint(x) & 0xFFFF0000u);
}
__device__ __forceinline__ uint32_t pack_lo_rn(float a, float b) {
    __nv_bfloat162 t = __floats2bfloat162_rn(a, b);
    return *(uint32_t*)&t;
}
__device__ __forceinline__ void prefetchL2(const void* p) {
    asm volatile("prefetch.global.L2 [%0];" :: "l"(p));
}
#define SMEM_SWIZZLE_128B(off) ((off) ^ (((off) >> 3) & 0x70))

// ---------------------------------------------------------------------------
// Kernel 0: detect edge_index element width (int64 vs int32).
// ---------------------------------------------------------------------------
__global__ void detect_kernel(const long long* __restrict__ ei64, int E, int n) {
    __shared__ int bad;
    if (threadIdx.x == 0) bad = 0;
    __syncthreads();
    int samples = min(4096, E);
    for (int i = threadIdx.x; i < samples; i += blockDim.x) {
        long long v = ei64[i];
        if (v < 0 || v >= (long long)n) atomicOr(&bad, 1);
    }
    __syncthreads();
    if (threadIdx.x == 0) g_is64 = bad ? 0 : 1;
}

// ---------------------------------------------------------------------------
// Kernel 0b: normalize edge list to int32 with self-loops appended.
// ---------------------------------------------------------------------------
__global__ void convert_edges_kernel(const void* __restrict__ ei_raw,
                                     int E, int n) {
    const int is64 = g_is64;
    const long long* ei64 = (const long long*)ei_raw;
    const int*       ei32 = (const int*)ei_raw;
    const int total = E + n;
    for (int i = blockIdx.x * blockDim.x + threadIdx.x; i < total;
         i += gridDim.x * blockDim.x) {
        int s, d;
        if (i < E) {
            if (is64) { s = (int)ei64[i]; d = (int)ei64[E + i]; }
            else      { s = ei32[i];      d = ei32[E + i]; }
        } else { s = i - E; d = s; }
        g_SRC[i] = s;
        g_DST[i] = d;
    }
}

// ---------------------------------------------------------------------------
// Kernel 1: per-node precompute of U and P (grid-stride) + out init fused.
// ---------------------------------------------------------------------------
__global__ void precompute_kernel(const float* __restrict__ x,
                                  const float* __restrict__ pos,
                                  const float* __restrict__ W1,
                                  const float* __restrict__ b1,
                                  float* __restrict__ out,
                                  int n) {
    __shared__ float W1s[35 * 64];
    __shared__ float b1s[64];
    for (int i = threadIdx.x; i < 35 * 64; i += blockDim.x) W1s[i] = W1[i];
    if (threadIdx.x < 64) b1s[threadIdx.x] = b1[threadIdx.x];
    __syncthreads();

    const int totalW = n * 64;
    for (int gid = blockIdx.x * blockDim.x + threadIdx.x; gid < totalW;
         gid += gridDim.x * blockDim.x) {
        int node = gid >> 6;
        int k = gid & 63;

        const float* xr = x + node * D_FEAT;
        float acc = b1s[k];
#pragma unroll
        for (int f = 0; f < D_FEAT; f++) acc = fmaf(xr[f], W1s[f * 64 + k], acc);
        float px = pos[node * 3 + 0];
        float py = pos[node * 3 + 1];
        float pz = pos[node * 3 + 2];
        float pp = px * W1s[32 * 64 + k];
        pp = fmaf(py, W1s[33 * 64 + k], pp);
        pp = fmaf(pz, W1s[34 * 64 + k], pp);

        g_U[node * 64 + k] = acc + pp;
        g_P[node * 64 + k] = pp;
        out[gid] = -FLT_MAX;
    }
}

__device__ __forceinline__ void atomicMaxF(float* addr, float v) {
    if (v >= 0.0f) atomicMax((int*)addr, __float_as_int(v));
    else           atomicMin((unsigned int*)addr, __float_as_uint(v));
}

// ---------------------------------------------------------------------------
// SMEM layout (dynamic, per CTA)
// ---------------------------------------------------------------------------
#define OFF_WHI 0            // W2^T hi: [64 n][64 k] bf16, 128B rows = 8192
#define OFF_WLO 8192         // 8192
#define OFF_HHI 16384        // H hi: [32 e][64 k] bf16, 128B rows = 4096
#define OFF_HLO 20480        // 4096
#define OFF_B2  24576        // 64 f32 = 256
#define OFF_DST 24832        // 32 int = 128
#define SMEM_BYTES 24960

// ---------------------------------------------------------------------------
// Kernel 3: persistent HMMA edge kernel.
// 128 threads = 4 warps = 2 warp-pairs; tile = 32 edges.
// Pair p owns edges [p*16, p*16+16); within a pair, warp `half` computes
// output cols [half*32, +32). W2^T bf16 hi/lo staged to smem ONCE per CTA.
// Per tile: gather + relu + bf16 hi/lo split -> swizzled H tiles -> ldmatrix
// A/B -> 48 mma per warp (D = Ahi@Bhi + Alo@Bhi + Ahi@Blo) -> scatter-max.
// ---------------------------------------------------------------------------
__global__ void __launch_bounds__(128, 5) edge_kernel(
    const float* __restrict__ W2,       // [64 k][64 n] row-major
    const float* __restrict__ b2,       // [64]
    float* __restrict__ out,            // [n, 64]
    int n, int E) {
    extern __shared__ __align__(128) char smem[];
    const uint32_t sb = smem_to_u32(smem);
    const int tid = threadIdx.x;
    const int lane = tid & 31;
    const int wid = tid >> 5;
    const int pairLocal = wid >> 1;     // 0..1
    const int half = wid & 1;           // col half
    const int n0 = half * 32;

    // ---- Stage W2^T hi/lo + b2 once per persistent CTA ----
    for (int idx = tid; idx < 64 * 64; idx += 128) {
        int nn = idx >> 6;
        int kk = idx & 63;
        float w = W2[kk * 64 + nn];
        uint32_t sw = SMEM_SWIZZLE_128B((uint32_t)(nn * 128 + kk * 2));
        *(__nv_bfloat16*)(smem + OFF_WHI + sw) =
            __ushort_as_bfloat16((unsigned short)(__float_as_uint(w) >> 16));
        *(__nv_bfloat16*)(smem + OFF_WLO + sw) = __float2bfloat16_rn(resid(w));
    }
    if (tid < 64) *(float*)(smem + OFF_B2 + tid * 4) = b2[tid];
    __syncthreads();

    int* dsts = (int*)(smem + OFF_DST);
    const float* b2s = (const float*)(smem + OFF_B2);

    const int total = E + n;
    const int nTiles = (total + TILE_E - 1) / TILE_E;

    // Gather-phase role
    const int c  = tid & 15;   // float4 chunk (cols c*4..c*4+3)
    const int es = tid >> 4;   // 8 edge slots per pass, 4 passes

    // GEMM-phase ldmatrix lane addressing (verified in R6)
    const int r8   = lane & 7;
    const int bit1 = (lane >> 3) & 1;
    const int bit2 = (lane >> 4) & 1;
    const uint32_t aRow = (uint32_t)((pairLocal * 16 + r8 + 8 * bit1) * 128);
    uint32_t aColSwz[4];
#pragma unroll
    for (int ks = 0; ks < 4; ks++)
        aColSwz[ks] = (uint32_t)((16 * bit2 + 32 * ks) ^ (r8 << 4));
    const int lB = lane & 15;
    const int rB = lB & 7;
    const int bitB = (lB >> 3) & 1;
    uint32_t bColSwz[4];
#pragma unroll
    for (int ks = 0; ks < 4; ks++)
        bColSwz[ks] = (uint32_t)((16 * bitB + 32 * ks) ^ (rB << 4));

    // Epilogue lane mapping
    const int g  = lane >> 2;   // 0..7
    const int t4 = lane & 3;    // 0..3
    float2 bias[4];
#pragma unroll
    for (int nt = 0; nt < 4; nt++)
        bias[nt] = *(const float2*)&b2s[n0 + nt * 8 + t4 * 2];

    for (int tile = blockIdx.x; tile < nTiles; tile += gridDim.x) {
        const int base = tile * TILE_E;

        // ---- Stage 1: gather + relu + bf16 hi/lo split into H tiles ----
#pragma unroll
        for (int j = 0; j < 4; j++) {
            int el = j * 8 + es;
            int eg = base + el;
            float4 h = make_float4(0.f, 0.f, 0.f, 0.f);
            int d = -1;
            if (eg < total) {
                int s = g_SRC[eg];
                d = g_DST[eg];
                float4 u = *(const float4*)&g_U[s * 64 + c * 4];
                float4 p = *(const float4*)&g_P[d * 64 + c * 4];
                h.x = fmaxf(u.x - p.x, 0.0f);
                h.y = fmaxf(u.y - p.y, 0.0f);
                h.z = fmaxf(u.z - p.z, 0.0f);
                h.w = fmaxf(u.w - p.w, 0.0f);
            }
            if (c == 0) {
                dsts[el] = d;
                if (d >= 0) {
                    prefetchL2(out + (long long)d * 64);
                    prefetchL2(out + (long long)d * 64 + 32);
                }
            }
            uint32_t sw = SMEM_SWIZZLE_128B((uint32_t)(el * 128 + c * 8));
            *(uint2*)(smem + OFF_HHI + sw) =
                make_uint2(pack_hi(h.x, h.y), pack_hi(h.z, h.w));
            *(uint2*)(smem + OFF_HLO + sw) =
                make_uint2(pack_lo_rn(resid(h.x), resid(h.y)),
                           pack_lo_rn(resid(h.z), resid(h.w)));
        }
        __syncthreads();

        // ---- Stage 2: HMMA GEMM (warp: 16 edges x 32 cols) ----
        float acc[4][4];
#pragma unroll
        for (int nt = 0; nt < 4; nt++)
#pragma unroll
            for (int q = 0; q < 4; q++) acc[nt][q] = 0.0f;

#pragma unroll
        for (int ks = 0; ks < 4; ks++) {
            uint32_t Ahi[4], Alo[4];
            ldm_x4(Ahi, sb + OFF_HHI + aRow + aColSwz[ks]);
            ldm_x4(Alo, sb + OFF_HLO + aRow + aColSwz[ks]);
#pragma unroll
            for (int nt = 0; nt < 4; nt++) {
                const uint32_t bRow = (uint32_t)((n0 + nt * 8 + rB) * 128);
                uint32_t bh0, bh1, bl0, bl1;
                ldm_x2(bh0, bh1, sb + OFF_WHI + bRow + bColSwz[ks]);
                ldm_x2(bl0, bl1, sb + OFF_WLO + bRow + bColSwz[ks]);
                mma_bf16(acc[nt], Ahi, bh0, bh1);
                mma_bf16(acc[nt], Alo, bh0, bh1);
                mma_bf16(acc[nt], Ahi, bl0, bl1);
            }
        }

        // ---- Stage 3: bias + pre-checked scatter-max ----
        const int dLo = dsts[pairLocal * 16 + g];
        const int dHi = dsts[pairLocal * 16 + g + 8];
        float* oLo = (dLo >= 0) ? out + (long long)dLo * 64 + n0 + t4 * 2 : nullptr;
        float* oHi = (dHi >= 0) ? out + (long long)dHi * 64 + n0 + t4 * 2 : nullptr;
#pragma unroll
        for (int nt = 0; nt < 4; nt++) {
            if (oLo) {
                float v0 = acc[nt][0] + bias[nt].x;
                float v1 = acc[nt][1] + bias[nt].y;
                float2 cur = *(const float2*)(oLo + nt * 8);
                if (v0 > cur.x) atomicMaxF(oLo + nt * 8, v0);
                if (v1 > cur.y) atomicMaxF(oLo + nt * 8 + 1, v1);
            }
            if (oHi) {
                float v2 = acc[nt][2] + bias[nt].x;
                float v3 = acc[nt][3] + bias[nt].y;
                float2 cur = *(const float2*)(oHi + nt * 8);
                if (v2 > cur.x) atomicMaxF(oHi + nt * 8, v2);
                if (v3 > cur.y) atomicMaxF(oHi + nt * 8 + 1, v3);
            }
        }
        __syncthreads();   // H tiles safe to overwrite next iteration
    }
}

// ---------------------------------------------------------------------------
// Launch
// ---------------------------------------------------------------------------
extern "C" void kernel_launch(void* const* d_in, const int* in_sizes, int n_in,
                              void* d_out, int out_size) {
    const float* x   = (const float*)d_in[0];    // [n, 32]
    const float* pos = (const float*)d_in[1];    // [n, 3]
    const void*  ei  = d_in[2];                  // [2, E] int64 or int32
    const float* W1  = (const float*)d_in[3];    // [35, 64]
    const float* b1  = (const float*)d_in[4];    // [64]
    const float* W2  = (const float*)d_in[5];    // [64, 64]
    const float* b2  = (const float*)d_in[6];    // [64]
    float*       out = (float*)d_out;            // [n, 64]

    int n = in_sizes[0] / D_FEAT;
    int E = in_sizes[2] / 2;

    cudaFuncSetAttribute(edge_kernel, cudaFuncAttributeMaxDynamicSharedMemorySize,
                         SMEM_BYTES);

    // 0) detect edge_index dtype, then normalize to int32 with self-loops
    detect_kernel<<<1, 256>>>((const long long*)ei, E, n);
    convert_edges_kernel<<<1480, 256>>>(ei, E, n);
    // 1) per-node precompute of U/P + out init (fused, grid-stride)
    precompute_kernel<<<1480, 256>>>(x, pos, W1, b1, out, n);
    // 2) persistent HMMA edge kernel: 5 CTAs/SM x 148 SMs
    edge_kernel<<<740, 128, SMEM_BYTES>>>(W2, b2, out, n, E);
}

// round 14
// speedup vs baseline: 1.2647x; 1.2647x over previous
#include <cuda_runtime.h>
#include <cuda_bf16.h>
#include <float.h>
#include <cstdint>

// Problem constants (fixed by the dataset)
#define MAX_NODES 100000
#define MAX_TOTAL 1703936   // E + n upper bound
#define D_FEAT 32
#define D_HID 64
#define D_OUT 64
#define TILE_E 64
#define H_STRIDE 68   // floats per H row (64 + pad, 16B-aligned)

// Scratch: per-node precomputed terms.
// U[j] = x_j @ W1[:32] + pos_j @ W1[32:35] + b1   (N x 64)
// P[i] = pos_i @ W1[32:35]                        (N x 64)
__device__ float g_U[MAX_NODES * D_HID];
__device__ float g_P[MAX_NODES * D_HID];
__device__ int g_is64;
// Normalized edge list (int32, self-loops appended): size total = E + n.
__device__ int g_SRC[MAX_TOTAL];
__device__ int g_DST[MAX_TOTAL];

// ---------------------------------------------------------------------------
// packed fp32x2 helpers (bit-exact pair of fp32 FMAs)
// ---------------------------------------------------------------------------
__device__ __forceinline__ void ffma2(unsigned long long& d,
                                      unsigned long long a,
                                      unsigned long long b) {
    asm("fma.rn.f32x2 %0, %1, %2, %0;" : "+l"(d) : "l"(a), "l"(b));
}
__device__ __forceinline__ unsigned long long packdup(float x) {
    unsigned long long r;
    asm("mov.b64 %0, {%1, %1};" : "=l"(r) : "f"(x));
    return r;
}
__device__ __forceinline__ void unpack2(unsigned long long v, float& lo, float& hi) {
    asm("mov.b64 {%0, %1}, %2;" : "=f"(lo), "=f"(hi) : "l"(v));
}
__device__ __forceinline__ void prefetchL2(const void* p) {
    asm volatile("prefetch.global.L2 [%0];" :: "l"(p));
}

// ---------------------------------------------------------------------------
// Kernel 0: detect edge_index element width (int64 vs int32).
// ---------------------------------------------------------------------------
__global__ void detect_kernel(const long long* __restrict__ ei64, int E, int n) {
    __shared__ int bad;
    if (threadIdx.x == 0) bad = 0;
    __syncthreads();
    int samples = min(4096, E);
    for (int i = threadIdx.x; i < samples; i += blockDim.x) {
        long long v = ei64[i];
        if (v < 0 || v >= (long long)n) atomicOr(&bad, 1);
    }
    __syncthreads();
    if (threadIdx.x == 0) g_is64 = bad ? 0 : 1;
}

// ---------------------------------------------------------------------------
// Kernel 0b: normalize edge list to int32 with self-loops appended.
// ---------------------------------------------------------------------------
__global__ void convert_edges_kernel(const void* __restrict__ ei_raw,
                                     int E, int n) {
    const int is64 = g_is64;
    const long long* ei64 = (const long long*)ei_raw;
    const int*       ei32 = (const int*)ei_raw;
    const int total = E + n;
    for (int i = blockIdx.x * blockDim.x + threadIdx.x; i < total;
         i += gridDim.x * blockDim.x) {
        int s, d;
        if (i < E) {
            if (is64) { s = (int)ei64[i]; d = (int)ei64[E + i]; }
            else      { s = ei32[i];      d = ei32[E + i]; }
        } else { s = i - E; d = s; }
        g_SRC[i] = s;
        g_DST[i] = d;
    }
}

// ---------------------------------------------------------------------------
// Kernel 1: per-node precompute of U and P (grid-stride) + out init fused.
// ---------------------------------------------------------------------------
__global__ void precompute_kernel(const float* __restrict__ x,
                                  const float* __restrict__ pos,
                                  const float* __restrict__ W1,
                                  const float* __restrict__ b1,
                                  float* __restrict__ out,
                                  int n) {
    __shared__ float W1s[35 * 64];
    __shared__ float b1s[64];
    for (int i = threadIdx.x; i < 35 * 64; i += blockDim.x) W1s[i] = W1[i];
    if (threadIdx.x < 64) b1s[threadIdx.x] = b1[threadIdx.x];
    __syncthreads();

    const int totalW = n * 64;
    for (int gid = blockIdx.x * blockDim.x + threadIdx.x; gid < totalW;
         gid += gridDim.x * blockDim.x) {
        int node = gid >> 6;
        int k = gid & 63;

        const float* xr = x + node * D_FEAT;
        float acc = b1s[k];
#pragma unroll
        for (int f = 0; f < D_FEAT; f++) acc = fmaf(xr[f], W1s[f * 64 + k], acc);
        float px = pos[node * 3 + 0];
        float py = pos[node * 3 + 1];
        float pz = pos[node * 3 + 2];
        float pp = px * W1s[32 * 64 + k];
        pp = fmaf(py, W1s[33 * 64 + k], pp);
        pp = fmaf(pz, W1s[34 * 64 + k], pp);

        g_U[node * 64 + k] = acc + pp;
        g_P[node * 64 + k] = pp;
        out[gid] = -FLT_MAX;
    }
}

__device__ __forceinline__ void atomicMaxF(float* addr, float v) {
    if (v >= 0.0f) atomicMax((int*)addr, __float_as_int(v));
    else           atomicMin((unsigned int*)addr, __float_as_uint(v));
}

// ---------------------------------------------------------------------------
// Kernel 3: persistent scalar-FFMA2 edge kernel (R10 structure + idx prefetch).
// 128 threads/CTA, 6 CTAs/SM, tile = 64 edges x 64 outputs.
// Thread tile = 4 edges x 8 outputs (proven layout).
// Edge indices for tile t+grid are prefetched into a double-buffered smem
// array AFTER the GEMM (LDG latency hides under the epilogue), so each tile's
// gather starts with an LDS broadcast instead of a dependent L2 LDG.
// ---------------------------------------------------------------------------
__global__ void __launch_bounds__(128, 6) edge_kernel(
    const float* __restrict__ W2,       // [64 k][64 n] row-major
    const float* __restrict__ b2,       // [64]
    float* __restrict__ out,            // [n, 64]
    int n, int E) {
    extern __shared__ float smem[];
    float* Hs  = smem;                       // TILE_E * H_STRIDE
    float* W2s = smem + TILE_E * H_STRIDE;   // 64 * 64
    float* b2s = W2s + 64 * 64;              // 64
    // idx double buffer: [2][128] ints; [b][0..63]=src, [b][64..127]=dst(-1=inv)
    int*   ibuf = (int*)(b2s + 64);

    const int tid = threadIdx.x;
    // ---- Stage W2 + b2 once per persistent CTA ----
    for (int i = tid; i < 64 * 64; i += 128) W2s[i] = W2[i];
    if (tid < 64) b2s[tid] = b2[tid];

    const int total = E + n;
    const int nTiles = (total + TILE_E - 1) / TILE_E;

    // ---- Preamble: load idx for first tile into buffer 0 ----
    {
        int t0 = blockIdx.x;
        if (t0 < nTiles) {
            int eg = t0 * TILE_E + (tid & 63);
            int v;
            if (tid < 64) v = (eg < total) ? g_SRC[eg] : 0;
            else          v = (eg < total) ? g_DST[eg] : -1;
            ibuf[tid] = v;
        }
    }
    __syncthreads();

    const int c  = tid & 15;   // float4 chunk of 64-wide row
    const int es = tid >> 4;   // 8 rows per pass
    const int cg = tid & 7;
    const int e0 = tid >> 3;        // 0..15
    const int kb1 = cg * 4;
    const int kb2 = 32 + cg * 4;
    const float4 bbA = *(const float4*)&b2s[kb1];
    const float4 bbB = *(const float4*)&b2s[kb2];

    int b = 0;
    for (int tile = blockIdx.x; tile < nTiles; tile += gridDim.x, b ^= 1) {
        const int* sbuf = ibuf + b * 128;
        const int* dbuf = sbuf + 64;

        // ---------------- Stage 1: gather + relu into Hs ----------------
        int dloc[8];
#pragma unroll
        for (int j = 0; j < TILE_E / 8; j++) {
            int el = j * 8 + es;
            int d = dbuf[el];
            dloc[j] = d;
            float4 h = make_float4(0.f, 0.f, 0.f, 0.f);
            if (d >= 0) {
                int s = sbuf[el];
                float4 u = *(const float4*)&g_U[s * 64 + c * 4];
                float4 p = *(const float4*)&g_P[d * 64 + c * 4];
                h.x = fmaxf(u.x - p.x, 0.0f);
                h.y = fmaxf(u.y - p.y, 0.0f);
                h.z = fmaxf(u.z - p.z, 0.0f);
                h.w = fmaxf(u.w - p.w, 0.0f);
                if (c == 0) {
                    prefetchL2(out + d * 64);
                    prefetchL2(out + d * 64 + 32);
                }
            }
            *(float4*)&Hs[el * H_STRIDE + c * 4] = h;
        }
        __syncthreads();

        // ---------------- Stage 2: GEMM (4 edges x 8 cols / thread) -------
        unsigned long long acc[4][4];
#pragma unroll
        for (int i = 0; i < 4; i++)
#pragma unroll
            for (int jq = 0; jq < 4; jq++) acc[i][jq] = 0ull;

#pragma unroll
        for (int m4 = 0; m4 < 16; m4++) {
            float h0[4], h1[4], h2[4], h3[4];
            {
                float4 t;
                t = *(const float4*)&Hs[(e0 +  0) * H_STRIDE + m4 * 4];
                h0[0] = t.x; h0[1] = t.y; h0[2] = t.z; h0[3] = t.w;
                t = *(const float4*)&Hs[(e0 + 16) * H_STRIDE + m4 * 4];
                h1[0] = t.x; h1[1] = t.y; h1[2] = t.z; h1[3] = t.w;
                t = *(const float4*)&Hs[(e0 + 32) * H_STRIDE + m4 * 4];
                h2[0] = t.x; h2[1] = t.y; h2[2] = t.z; h2[3] = t.w;
                t = *(const float4*)&Hs[(e0 + 48) * H_STRIDE + m4 * 4];
                h3[0] = t.x; h3[1] = t.y; h3[2] = t.z; h3[3] = t.w;
            }
#pragma unroll
            for (int mm = 0; mm < 4; mm++) {
                const int m = m4 * 4 + mm;
                ulonglong2 wA = *(const ulonglong2*)&W2s[m * 64 + kb1];
                ulonglong2 wB = *(const ulonglong2*)&W2s[m * 64 + kb2];
                unsigned long long hb;
                hb = packdup(h0[mm]);
                ffma2(acc[0][0], hb, wA.x); ffma2(acc[0][1], hb, wA.y);
                ffma2(acc[0][2], hb, wB.x); ffma2(acc[0][3], hb, wB.y);
                hb = packdup(h1[mm]);
                ffma2(acc[1][0], hb, wA.x); ffma2(acc[1][1], hb, wA.y);
                ffma2(acc[1][2], hb, wB.x); ffma2(acc[1][3], hb, wB.y);
                hb = packdup(h2[mm]);
                ffma2(acc[2][0], hb, wA.x); ffma2(acc[2][1], hb, wA.y);
                ffma2(acc[2][2], hb, wB.x); ffma2(acc[2][3], hb, wB.y);
                hb = packdup(h3[mm]);
                ffma2(acc[3][0], hb, wA.x); ffma2(acc[3][1], hb, wA.y);
                ffma2(acc[3][2], hb, wB.x); ffma2(acc[3][3], hb, wB.y);
            }
        }

        // ---- Prefetch next tile's idx (LDG latency hides under epilogue) --
        int nt = tile + gridDim.x;
        int pv = 0;
        bool doPref = (nt < nTiles);
        if (doPref) {
            int eg = nt * TILE_E + (tid & 63);
            if (tid < 64) pv = (eg < total) ? g_SRC[eg] : 0;
            else          pv = (eg < total) ? g_DST[eg] : -1;
        }

        // ---------------- Stage 3: scatter-max ----------------
#pragma unroll
        for (int i = 0; i < 4; i++) {
            // GEMM-phase edge rows are e0 + 16*i; their dsts sit in dbuf,
            // read via LDS broadcast (cheap).
            int d = dbuf[e0 + 16 * i];
            if (d < 0) continue;
            float v0, v1, v2, v3, v4, v5, v6, v7;
            unpack2(acc[i][0], v0, v1);
            unpack2(acc[i][1], v2, v3);
            unpack2(acc[i][2], v4, v5);
            unpack2(acc[i][3], v6, v7);
            v0 += bbA.x; v1 += bbA.y; v2 += bbA.z; v3 += bbA.w;
            v4 += bbB.x; v5 += bbB.y; v6 += bbB.z; v7 += bbB.w;
            float* oA = out + d * 64 + kb1;
            float* oB = out + d * 64 + kb2;
            float4 curA = *(const float4*)oA;
            float4 curB = *(const float4*)oB;
            if (v0 > curA.x) atomicMaxF(oA + 0, v0);
            if (v1 > curA.y) atomicMaxF(oA + 1, v1);
            if (v2 > curA.z) atomicMaxF(oA + 2, v2);
            if (v3 > curA.w) atomicMaxF(oA + 3, v3);
            if (v4 > curB.x) atomicMaxF(oB + 0, v4);
            if (v5 > curB.y) atomicMaxF(oB + 1, v5);
            if (v6 > curB.z) atomicMaxF(oB + 2, v6);
            if (v7 > curB.w) atomicMaxF(oB + 3, v7);
        }

        // Store prefetched idx into the alternate buffer before the sync.
        if (doPref) ibuf[(b ^ 1) * 128 + tid] = pv;
        __syncthreads();   // Hs + ibuf handoff safe for next tile
        (void)dloc;
    }
}

// ---------------------------------------------------------------------------
// Launch
// ---------------------------------------------------------------------------
extern "C" void kernel_launch(void* const* d_in, const int* in_sizes, int n_in,
                              void* d_out, int out_size) {
    const float* x   = (const float*)d_in[0];    // [n, 32]
    const float* pos = (const float*)d_in[1];    // [n, 3]
    const void*  ei  = d_in[2];                  // [2, E] int64 or int32
    const float* W1  = (const float*)d_in[3];    // [35, 64]
    const float* b1  = (const float*)d_in[4];    // [64]
    const float* W2  = (const float*)d_in[5];    // [64, 64]
    const float* b2  = (const float*)d_in[6];    // [64]
    float*       out = (float*)d_out;            // [n, 64]

    int n = in_sizes[0] / D_FEAT;
    int E = in_sizes[2] / 2;

    const int smemBytes = (TILE_E * H_STRIDE + 64 * 64 + 64) * 4 + 2 * 128 * 4;
    cudaFuncSetAttribute(edge_kernel, cudaFuncAttributeMaxDynamicSharedMemorySize,
                         smemBytes);

    // 0) detect edge_index dtype, then normalize to int32 with self-loops
    detect_kernel<<<1, 256>>>((const long long*)ei, E, n);
    convert_edges_kernel<<<1480, 256>>>(ei, E, n);
    // 1) per-node precompute of U/P + out init (fused, grid-stride)
    precompute_kernel<<<1480, 256>>>(x, pos, W1, b1, out, n);
    // 2) persistent edge kernel: 6 CTAs/SM x 148 SMs
    edge_kernel<<<888, 128, smemBytes>>>(W2, b2, out, n, E);
}

// round 15
// speedup vs baseline: 1.2863x; 1.0171x over previous
#include <cuda_runtime.h>
#include <cuda_bf16.h>
#include <float.h>
#include <cstdint>

// Problem constants (fixed by the dataset)
#define MAX_NODES 100000
#define MAX_TOTAL 1703936   // E + n upper bound
#define D_FEAT 32
#define D_HID 64
#define D_OUT 64
#define TILE_E 64
#define H_STRIDE 68   // floats per H row (64 + pad, 16B-aligned)

// Scratch: per-node precomputed terms.
// U[j] = x_j @ W1[:32] + pos_j @ W1[32:35] + b1   (N x 64)
// P[i] = pos_i @ W1[32:35]                        (N x 64)
__device__ float g_U[MAX_NODES * D_HID];
__device__ float g_P[MAX_NODES * D_HID];
// Normalized edge list (int32, self-loops appended): size total = E + n.
__device__ int g_SRC[MAX_TOTAL];
__device__ int g_DST[MAX_TOTAL];

// ---------------------------------------------------------------------------
// packed fp32x2 helpers (bit-exact pair of fp32 FMAs)
// ---------------------------------------------------------------------------
__device__ __forceinline__ void ffma2(unsigned long long& d,
                                      unsigned long long a,
                                      unsigned long long b) {
    asm("fma.rn.f32x2 %0, %1, %2, %0;" : "+l"(d) : "l"(a), "l"(b));
}
__device__ __forceinline__ unsigned long long packdup(float x) {
    unsigned long long r;
    asm("mov.b64 %0, {%1, %1};" : "=l"(r) : "f"(x));
    return r;
}
__device__ __forceinline__ unsigned long long pack2f(float a, float b) {
    unsigned long long r;
    asm("mov.b64 %0, {%1, %2};" : "=l"(r) : "f"(a), "f"(b));
    return r;
}
__device__ __forceinline__ void unpack2(unsigned long long v, float& lo, float& hi) {
    asm("mov.b64 {%0, %1}, %2;" : "=f"(lo), "=f"(hi) : "l"(v));
}
__device__ __forceinline__ void prefetchL2(const void* p) {
    asm volatile("prefetch.global.L2 [%0];" :: "l"(p));
}

// ---------------------------------------------------------------------------
// Kernel 1: fused setup — per-block dtype detect + edge normalize + U/P
// precompute + out init. One launch instead of three.
// ---------------------------------------------------------------------------
__global__ void setup_kernel(const void* __restrict__ ei_raw,
                             const float* __restrict__ x,
                             const float* __restrict__ pos,
                             const float* __restrict__ W1,
                             const float* __restrict__ b1,
                             float* __restrict__ out,
                             int E, int n) {
    __shared__ float W1s[35 * 64];
    __shared__ float b1s[64];
    __shared__ int s_is64;

    // ---- Block-local dtype detection (samples are L2-broadcast; for int32
    // data an int64 interpretation is out of [0,n) with ~certainty). ----
    if (threadIdx.x == 0) s_is64 = 1;
    for (int i = threadIdx.x; i < 35 * 64; i += blockDim.x) W1s[i] = W1[i];
    if (threadIdx.x < 64) b1s[threadIdx.x] = b1[threadIdx.x];
    __syncthreads();
    {
        const long long* ei64 = (const long long*)ei_raw;
        int samples = min(256, E);
        int bad = 0;
        for (int i = threadIdx.x; i < samples; i += blockDim.x) {
            long long v = ei64[i];
            if (v < 0 || v >= (long long)n) bad = 1;
        }
        if (__syncthreads_or(bad)) {
            if (threadIdx.x == 0) s_is64 = 0;
        }
        __syncthreads();
    }
    const int is64 = s_is64;

    // ---- Loop A: normalize edge list (int32, self-loops appended) ----
    {
        const long long* ei64 = (const long long*)ei_raw;
        const int*       ei32 = (const int*)ei_raw;
        const int total = E + n;
        for (int i = blockIdx.x * blockDim.x + threadIdx.x; i < total;
             i += gridDim.x * blockDim.x) {
            int s, d;
            if (i < E) {
                if (is64) { s = (int)ei64[i]; d = (int)ei64[E + i]; }
                else      { s = ei32[i];      d = ei32[E + i]; }
            } else { s = i - E; d = s; }
            g_SRC[i] = s;
            g_DST[i] = d;
        }
    }

    // ---- Loop B: per-node U/P precompute + out init ----
    const int totalW = n * 64;
    for (int gid = blockIdx.x * blockDim.x + threadIdx.x; gid < totalW;
         gid += gridDim.x * blockDim.x) {
        int node = gid >> 6;
        int k = gid & 63;

        const float* xr = x + node * D_FEAT;
        float acc = b1s[k];
#pragma unroll
        for (int f = 0; f < D_FEAT; f++) acc = fmaf(xr[f], W1s[f * 64 + k], acc);
        float px = pos[node * 3 + 0];
        float py = pos[node * 3 + 1];
        float pz = pos[node * 3 + 2];
        float pp = px * W1s[32 * 64 + k];
        pp = fmaf(py, W1s[33 * 64 + k], pp);
        pp = fmaf(pz, W1s[34 * 64 + k], pp);

        g_U[node * 64 + k] = acc + pp;
        g_P[node * 64 + k] = pp;
        out[gid] = -FLT_MAX;
    }
}

__device__ __forceinline__ void atomicMaxF(float* addr, float v) {
    if (v >= 0.0f) atomicMax((int*)addr, __float_as_int(v));
    else           atomicMin((unsigned int*)addr, __float_as_uint(v));
}

// ---------------------------------------------------------------------------
// Kernel 2: persistent scalar-FFMA2 edge kernel (R14 structure).
// 128 threads/CTA, 6 CTAs/SM, tile = 64 edges x 64 outputs.
// Thread tile = 4 edges x 8 outputs. Edge indices double-buffered in smem
// (prefetched under the epilogue). Bias is folded into accumulator init.
// ---------------------------------------------------------------------------
__global__ void __launch_bounds__(128, 6) edge_kernel(
    const float* __restrict__ W2,       // [64 k][64 n] row-major
    const float* __restrict__ b2,       // [64]
    float* __restrict__ out,            // [n, 64]
    int n, int E) {
    extern __shared__ float smem[];
    float* Hs  = smem;                       // TILE_E * H_STRIDE
    float* W2s = smem + TILE_E * H_STRIDE;   // 64 * 64
    float* b2s = W2s + 64 * 64;              // 64
    // idx double buffer: [2][128] ints; [b][0..63]=src, [b][64..127]=dst(-1=inv)
    int*   ibuf = (int*)(b2s + 64);

    const int tid = threadIdx.x;
    // ---- Stage W2 + b2 once per persistent CTA ----
    for (int i = tid; i < 64 * 64; i += 128) W2s[i] = W2[i];
    if (tid < 64) b2s[tid] = b2[tid];

    const int total = E + n;
    const int nTiles = (total + TILE_E - 1) / TILE_E;

    // ---- Preamble: load idx for first tile into buffer 0 ----
    {
        int t0 = blockIdx.x;
        if (t0 < nTiles) {
            int eg = t0 * TILE_E + (tid & 63);
            int v;
            if (tid < 64) v = (eg < total) ? g_SRC[eg] : 0;
            else          v = (eg < total) ? g_DST[eg] : -1;
            ibuf[tid] = v;
        }
    }
    __syncthreads();

    const int c  = tid & 15;   // float4 chunk of 64-wide row
    const int es = tid >> 4;   // 8 rows per pass
    const int cg = tid & 7;
    const int e0 = tid >> 3;        // 0..15
    const int kb1 = cg * 4;
    const int kb2 = 32 + cg * 4;
    const float4 bbA = *(const float4*)&b2s[kb1];
    const float4 bbB = *(const float4*)&b2s[kb2];
    const unsigned long long bi0 = pack2f(bbA.x, bbA.y);
    const unsigned long long bi1 = pack2f(bbA.z, bbA.w);
    const unsigned long long bi2 = pack2f(bbB.x, bbB.y);
    const unsigned long long bi3 = pack2f(bbB.z, bbB.w);

    int b = 0;
    for (int tile = blockIdx.x; tile < nTiles; tile += gridDim.x, b ^= 1) {
        const int* sbuf = ibuf + b * 128;
        const int* dbuf = sbuf + 64;

        // ---------------- Stage 1: gather + relu into Hs ----------------
#pragma unroll
        for (int j = 0; j < TILE_E / 8; j++) {
            int el = j * 8 + es;
            int d = dbuf[el];
            float4 h = make_float4(0.f, 0.f, 0.f, 0.f);
            if (d >= 0) {
                int s = sbuf[el];
                float4 u = *(const float4*)&g_U[s * 64 + c * 4];
                float4 p = *(const float4*)&g_P[d * 64 + c * 4];
                h.x = fmaxf(u.x - p.x, 0.0f);
                h.y = fmaxf(u.y - p.y, 0.0f);
                h.z = fmaxf(u.z - p.z, 0.0f);
                h.w = fmaxf(u.w - p.w, 0.0f);
                if (c == 0) {
                    prefetchL2(out + d * 64);
                    prefetchL2(out + d * 64 + 32);
                }
            }
            *(float4*)&Hs[el * H_STRIDE + c * 4] = h;
        }
        __syncthreads();

        // ---------------- Stage 2: GEMM (4 edges x 8 cols / thread) -------
        // Accumulators start at the bias (fp32 reassociation only).
        unsigned long long acc[4][4];
#pragma unroll
        for (int i = 0; i < 4; i++) {
            acc[i][0] = bi0; acc[i][1] = bi1; acc[i][2] = bi2; acc[i][3] = bi3;
        }

#pragma unroll
        for (int m4 = 0; m4 < 16; m4++) {
            float h0[4], h1[4], h2[4], h3[4];
            {
                float4 t;
                t = *(const float4*)&Hs[(e0 +  0) * H_STRIDE + m4 * 4];
                h0[0] = t.x; h0[1] = t.y; h0[2] = t.z; h0[3] = t.w;
                t = *(const float4*)&Hs[(e0 + 16) * H_STRIDE + m4 * 4];
                h1[0] = t.x; h1[1] = t.y; h1[2] = t.z; h1[3] = t.w;
                t = *(const float4*)&Hs[(e0 + 32) * H_STRIDE + m4 * 4];
                h2[0] = t.x; h2[1] = t.y; h2[2] = t.z; h2[3] = t.w;
                t = *(const float4*)&Hs[(e0 + 48) * H_STRIDE + m4 * 4];
                h3[0] = t.x; h3[1] = t.y; h3[2] = t.z; h3[3] = t.w;
            }
#pragma unroll
            for (int mm = 0; mm < 4; mm++) {
                const int m = m4 * 4 + mm;
                ulonglong2 wA = *(const ulonglong2*)&W2s[m * 64 + kb1];
                ulonglong2 wB = *(const ulonglong2*)&W2s[m * 64 + kb2];
                unsigned long long hb;
                hb = packdup(h0[mm]);
                ffma2(acc[0][0], hb, wA.x); ffma2(acc[0][1], hb, wA.y);
                ffma2(acc[0][2], hb, wB.x); ffma2(acc[0][3], hb, wB.y);
                hb = packdup(h1[mm]);
                ffma2(acc[1][0], hb, wA.x); ffma2(acc[1][1], hb, wA.y);
                ffma2(acc[1][2], hb, wB.x); ffma2(acc[1][3], hb, wB.y);
                hb = packdup(h2[mm]);
                ffma2(acc[2][0], hb, wA.x); ffma2(acc[2][1], hb, wA.y);
                ffma2(acc[2][2], hb, wB.x); ffma2(acc[2][3], hb, wB.y);
                hb = packdup(h3[mm]);
                ffma2(acc[3][0], hb, wA.x); ffma2(acc[3][1], hb, wA.y);
                ffma2(acc[3][2], hb, wB.x); ffma2(acc[3][3], hb, wB.y);
            }
        }

        // ---- Prefetch next tile's idx (LDG latency hides under epilogue) --
        int nt = tile + gridDim.x;
        int pv = 0;
        bool doPref = (nt < nTiles);
        if (doPref) {
            int eg = nt * TILE_E + (tid & 63);
            if (tid < 64) pv = (eg < total) ? g_SRC[eg] : 0;
            else          pv = (eg < total) ? g_DST[eg] : -1;
        }

        // ---------------- Stage 3: scatter-max ----------------
#pragma unroll
        for (int i = 0; i < 4; i++) {
            int d = dbuf[e0 + 16 * i];
            if (d < 0) continue;
            float v0, v1, v2, v3, v4, v5, v6, v7;
            unpack2(acc[i][0], v0, v1);
            unpack2(acc[i][1], v2, v3);
            unpack2(acc[i][2], v4, v5);
            unpack2(acc[i][3], v6, v7);
            float* oA = out + d * 64 + kb1;
            float* oB = out + d * 64 + kb2;
            float4 curA = *(const float4*)oA;
            float4 curB = *(const float4*)oB;
            if (v0 > curA.x) atomicMaxF(oA + 0, v0);
            if (v1 > curA.y) atomicMaxF(oA + 1, v1);
            if (v2 > curA.z) atomicMaxF(oA + 2, v2);
            if (v3 > curA.w) atomicMaxF(oA + 3, v3);
            if (v4 > curB.x) atomicMaxF(oB + 0, v4);
            if (v5 > curB.y) atomicMaxF(oB + 1, v5);
            if (v6 > curB.z) atomicMaxF(oB + 2, v6);
            if (v7 > curB.w) atomicMaxF(oB + 3, v7);
        }

        // Store prefetched idx into the alternate buffer before the sync.
        if (doPref) ibuf[(b ^ 1) * 128 + tid] = pv;
        __syncthreads();   // Hs + ibuf handoff safe for next tile
    }
}

// ---------------------------------------------------------------------------
// Launch
// ---------------------------------------------------------------------------
extern "C" void kernel_launch(void* const* d_in, const int* in_sizes, int n_in,
                              void* d_out, int out_size) {
    const float* x   = (const float*)d_in[0];    // [n, 32]
    const float* pos = (const float*)d_in[1];    // [n, 3]
    const void*  ei  = d_in[2];                  // [2, E] int64 or int32
    const float* W1  = (const float*)d_in[3];    // [35, 64]
    const float* b1  = (const float*)d_in[4];    // [64]
    const float* W2  = (const float*)d_in[5];    // [64, 64]
    const float* b2  = (const float*)d_in[6];    // [64]
    float*       out = (float*)d_out;            // [n, 64]

    int n = in_sizes[0] / D_FEAT;
    int E = in_sizes[2] / 2;

    const int smemBytes = (TILE_E * H_STRIDE + 64 * 64 + 64) * 4 + 2 * 128 * 4;
    cudaFuncSetAttribute(edge_kernel, cudaFuncAttributeMaxDynamicSharedMemorySize,
                         smemBytes);

    // 1) fused setup: dtype detect + edge normalize + U/P precompute + init
    setup_kernel<<<1480, 256>>>(ei, x, pos, W1, b1, out, E, n);
    // 2) persistent edge kernel: 6 CTAs/SM x 148 SMs
    edge_kernel<<<888, 128, smemBytes>>>(W2, b2, out, n, E);
}

// round 16
// speedup vs baseline: 1.3590x; 1.0565x over previous
#include <cuda_runtime.h>
#include <cuda_bf16.h>
#include <float.h>
#include <cstdint>

// Problem constants (fixed by the dataset)
#define MAX_NODES 100000
#define MAX_TOTAL 1703936   // E + n upper bound
#define D_FEAT 32
#define D_HID 64
#define D_OUT 64
#define TILE_E 64
#define H_STRIDE 68   // floats per H row (64 + pad, 16B-aligned)

// Scratch: per-node precomputed terms.
// U[j] = x_j @ W1[:32] + pos_j @ W1[32:35] + b1   (N x 64)
// P[i] = pos_i @ W1[32:35]                        (N x 64)
__device__ float g_U[MAX_NODES * D_HID];
__device__ float g_P[MAX_NODES * D_HID];
// Normalized edge list (int32, self-loops appended): size total = E + n.
__device__ int g_SRC[MAX_TOTAL];
__device__ int g_DST[MAX_TOTAL];

// ---------------------------------------------------------------------------
// packed fp32x2 helpers (each is exactly two independent .rn fp32 ops)
// ---------------------------------------------------------------------------
__device__ __forceinline__ void ffma2(unsigned long long& d,
                                      unsigned long long a,
                                      unsigned long long b) {
    asm("fma.rn.f32x2 %0, %1, %2, %0;" : "+l"(d) : "l"(a), "l"(b));
}
__device__ __forceinline__ unsigned long long mul2(unsigned long long a,
                                                   unsigned long long b) {
    unsigned long long r;
    asm("mul.rn.f32x2 %0, %1, %2;" : "=l"(r) : "l"(a), "l"(b));
    return r;
}
__device__ __forceinline__ unsigned long long add2(unsigned long long a,
                                                   unsigned long long b) {
    unsigned long long r;
    asm("add.rn.f32x2 %0, %1, %2;" : "=l"(r) : "l"(a), "l"(b));
    return r;
}
__device__ __forceinline__ unsigned long long packdup(float x) {
    unsigned long long r;
    asm("mov.b64 %0, {%1, %1};" : "=l"(r) : "f"(x));
    return r;
}
__device__ __forceinline__ unsigned long long pack2f(float a, float b) {
    unsigned long long r;
    asm("mov.b64 %0, {%1, %2};" : "=l"(r) : "f"(a), "f"(b));
    return r;
}
__device__ __forceinline__ void unpack2(unsigned long long v, float& lo, float& hi) {
    asm("mov.b64 {%0, %1}, %2;" : "=f"(lo), "=f"(hi) : "l"(v));
}
__device__ __forceinline__ void prefetchL2(const void* p) {
    asm volatile("prefetch.global.L2 [%0];" :: "l"(p));
}

// ---------------------------------------------------------------------------
// Kernel 1: fused setup — per-block dtype detect + edge normalize + U/P
// precompute (4 outputs/thread, packed f32x2; bit-exact chains) + out init.
// ---------------------------------------------------------------------------
__global__ void setup_kernel(const void* __restrict__ ei_raw,
                             const float* __restrict__ x,
                             const float* __restrict__ pos,
                             const float* __restrict__ W1,
                             const float* __restrict__ b1,
                             float* __restrict__ out,
                             int E, int n) {
    __shared__ float W1s[35 * 64];
    __shared__ float b1s[64];
    __shared__ int s_is64;

    if (threadIdx.x == 0) s_is64 = 1;
    for (int i = threadIdx.x; i < 35 * 64; i += blockDim.x) W1s[i] = W1[i];
    if (threadIdx.x < 64) b1s[threadIdx.x] = b1[threadIdx.x];
    __syncthreads();
    // ---- Block-local dtype detection (int32 data read as int64 lands out
    // of [0,n) with ~certainty over 256 samples). ----
    {
        const long long* ei64 = (const long long*)ei_raw;
        int samples = min(256, E);
        int bad = 0;
        for (int i = threadIdx.x; i < samples; i += blockDim.x) {
            long long v = ei64[i];
            if (v < 0 || v >= (long long)n) bad = 1;
        }
        if (__syncthreads_or(bad)) {
            if (threadIdx.x == 0) s_is64 = 0;
        }
        __syncthreads();
    }
    const int is64 = s_is64;

    // ---- Loop A: normalize edge list (int32, self-loops appended) ----
    {
        const long long* ei64 = (const long long*)ei_raw;
        const int*       ei32 = (const int*)ei_raw;
        const int total = E + n;
        for (int i = blockIdx.x * blockDim.x + threadIdx.x; i < total;
             i += gridDim.x * blockDim.x) {
            int s, d;
            if (i < E) {
                if (is64) { s = (int)ei64[i]; d = (int)ei64[E + i]; }
                else      { s = ei32[i];      d = ei32[E + i]; }
            } else { s = i - E; d = s; }
            g_SRC[i] = s;
            g_DST[i] = d;
        }
    }

    // ---- Loop B: U/P precompute + out init, 4 outputs per thread ----
    // Thread owns (node, k4*4..k4*4+3). Packed f32x2 accumulators; per-lane
    // chain order identical to the scalar version (bit-exact).
    const int totalQ = n * 16;
    for (int q = blockIdx.x * blockDim.x + threadIdx.x; q < totalQ;
         q += gridDim.x * blockDim.x) {
        int node = q >> 4;
        int k4 = (q & 15) * 4;

        const float4* xr = (const float4*)(x + node * D_FEAT);
        unsigned long long acc01 = pack2f(b1s[k4], b1s[k4 + 1]);
        unsigned long long acc23 = pack2f(b1s[k4 + 2], b1s[k4 + 3]);
#pragma unroll
        for (int f4 = 0; f4 < 8; f4++) {
            float4 xv = xr[f4];
            ulonglong2 w0 = *(const ulonglong2*)&W1s[(f4 * 4 + 0) * 64 + k4];
            ulonglong2 w1 = *(const ulonglong2*)&W1s[(f4 * 4 + 1) * 64 + k4];
            ulonglong2 w2 = *(const ulonglong2*)&W1s[(f4 * 4 + 2) * 64 + k4];
            ulonglong2 w3 = *(const ulonglong2*)&W1s[(f4 * 4 + 3) * 64 + k4];
            unsigned long long xb;
            xb = packdup(xv.x); ffma2(acc01, xb, w0.x); ffma2(acc23, xb, w0.y);
            xb = packdup(xv.y); ffma2(acc01, xb, w1.x); ffma2(acc23, xb, w1.y);
            xb = packdup(xv.z); ffma2(acc01, xb, w2.x); ffma2(acc23, xb, w2.y);
            xb = packdup(xv.w); ffma2(acc01, xb, w3.x); ffma2(acc23, xb, w3.y);
        }
        float px = pos[node * 3 + 0];
        float py = pos[node * 3 + 1];
        float pz = pos[node * 3 + 2];
        ulonglong2 w32 = *(const ulonglong2*)&W1s[32 * 64 + k4];
        ulonglong2 w33 = *(const ulonglong2*)&W1s[33 * 64 + k4];
        ulonglong2 w34 = *(const ulonglong2*)&W1s[34 * 64 + k4];
        unsigned long long pxb = packdup(px);
        unsigned long long pyb = packdup(py);
        unsigned long long pzb = packdup(pz);
        unsigned long long pp01 = mul2(pxb, w32.x);
        unsigned long long pp23 = mul2(pxb, w32.y);
        ffma2(pp01, pyb, w33.x); ffma2(pp23, pyb, w33.y);
        ffma2(pp01, pzb, w34.x); ffma2(pp23, pzb, w34.y);

        unsigned long long u01 = add2(acc01, pp01);
        unsigned long long u23 = add2(acc23, pp23);

        float4 uv, pv;
        unpack2(u01, uv.x, uv.y);
        unpack2(u23, uv.z, uv.w);
        unpack2(pp01, pv.x, pv.y);
        unpack2(pp23, pv.z, pv.w);
        *(float4*)&g_U[node * 64 + k4] = uv;
        *(float4*)&g_P[node * 64 + k4] = pv;
        *(float4*)&out[node * 64 + k4] =
            make_float4(-FLT_MAX, -FLT_MAX, -FLT_MAX, -FLT_MAX);
    }
}

__device__ __forceinline__ void atomicMaxF(float* addr, float v) {
    if (v >= 0.0f) atomicMax((int*)addr, __float_as_int(v));
    else           atomicMin((unsigned int*)addr, __float_as_uint(v));
}

// ---------------------------------------------------------------------------
// Kernel 2: persistent scalar-FFMA2 edge kernel (R15 structure, unchanged).
// 128 threads/CTA, 6 CTAs/SM, tile = 64 edges x 64 outputs.
// Thread tile = 4 edges x 8 outputs. Edge indices double-buffered in smem
// (prefetched under the epilogue). Bias folded into accumulator init.
// ---------------------------------------------------------------------------
__global__ void __launch_bounds__(128, 6) edge_kernel(
    const float* __restrict__ W2,       // [64 k][64 n] row-major
    const float* __restrict__ b2,       // [64]
    float* __restrict__ out,            // [n, 64]
    int n, int E) {
    extern __shared__ float smem[];
    float* Hs  = smem;                       // TILE_E * H_STRIDE
    float* W2s = smem + TILE_E * H_STRIDE;   // 64 * 64
    float* b2s = W2s + 64 * 64;              // 64
    // idx double buffer: [2][128] ints; [b][0..63]=src, [b][64..127]=dst(-1=inv)
    int*   ibuf = (int*)(b2s + 64);

    const int tid = threadIdx.x;
    // ---- Stage W2 + b2 once per persistent CTA ----
    for (int i = tid; i < 64 * 64; i += 128) W2s[i] = W2[i];
    if (tid < 64) b2s[tid] = b2[tid];

    const int total = E + n;
    const int nTiles = (total + TILE_E - 1) / TILE_E;

    // ---- Preamble: load idx for first tile into buffer 0 ----
    {
        int t0 = blockIdx.x;
        if (t0 < nTiles) {
            int eg = t0 * TILE_E + (tid & 63);
            int v;
            if (tid < 64) v = (eg < total) ? g_SRC[eg] : 0;
            else          v = (eg < total) ? g_DST[eg] : -1;
            ibuf[tid] = v;
        }
    }
    __syncthreads();

    const int c  = tid & 15;   // float4 chunk of 64-wide row
    const int es = tid >> 4;   // 8 rows per pass
    const int cg = tid & 7;
    const int e0 = tid >> 3;        // 0..15
    const int kb1 = cg * 4;
    const int kb2 = 32 + cg * 4;
    const float4 bbA = *(const float4*)&b2s[kb1];
    const float4 bbB = *(const float4*)&b2s[kb2];
    const unsigned long long bi0 = pack2f(bbA.x, bbA.y);
    const unsigned long long bi1 = pack2f(bbA.z, bbA.w);
    const unsigned long long bi2 = pack2f(bbB.x, bbB.y);
    const unsigned long long bi3 = pack2f(bbB.z, bbB.w);

    int b = 0;
    for (int tile = blockIdx.x; tile < nTiles; tile += gridDim.x, b ^= 1) {
        const int* sbuf = ibuf + b * 128;
        const int* dbuf = sbuf + 64;

        // ---------------- Stage 1: gather + relu into Hs ----------------
#pragma unroll
        for (int j = 0; j < TILE_E / 8; j++) {
            int el = j * 8 + es;
            int d = dbuf[el];
            float4 h = make_float4(0.f, 0.f, 0.f, 0.f);
            if (d >= 0) {
                int s = sbuf[el];
                float4 u = *(const float4*)&g_U[s * 64 + c * 4];
                float4 p = *(const float4*)&g_P[d * 64 + c * 4];
                h.x = fmaxf(u.x - p.x, 0.0f);
                h.y = fmaxf(u.y - p.y, 0.0f);
                h.z = fmaxf(u.z - p.z, 0.0f);
                h.w = fmaxf(u.w - p.w, 0.0f);
                if (c == 0) {
                    prefetchL2(out + d * 64);
                    prefetchL2(out + d * 64 + 32);
                }
            }
            *(float4*)&Hs[el * H_STRIDE + c * 4] = h;
        }
        __syncthreads();

        // ---------------- Stage 2: GEMM (4 edges x 8 cols / thread) -------
        unsigned long long acc[4][4];
#pragma unroll
        for (int i = 0; i < 4; i++) {
            acc[i][0] = bi0; acc[i][1] = bi1; acc[i][2] = bi2; acc[i][3] = bi3;
        }

#pragma unroll
        for (int m4 = 0; m4 < 16; m4++) {
            float h0[4], h1[4], h2[4], h3[4];
            {
                float4 t;
                t = *(const float4*)&Hs[(e0 +  0) * H_STRIDE + m4 * 4];
                h0[0] = t.x; h0[1] = t.y; h0[2] = t.z; h0[3] = t.w;
                t = *(const float4*)&Hs[(e0 + 16) * H_STRIDE + m4 * 4];
                h1[0] = t.x; h1[1] = t.y; h1[2] = t.z; h1[3] = t.w;
                t = *(const float4*)&Hs[(e0 + 32) * H_STRIDE + m4 * 4];
                h2[0] = t.x; h2[1] = t.y; h2[2] = t.z; h2[3] = t.w;
                t = *(const float4*)&Hs[(e0 + 48) * H_STRIDE + m4 * 4];
                h3[0] = t.x; h3[1] = t.y; h3[2] = t.z; h3[3] = t.w;
            }
#pragma unroll
            for (int mm = 0; mm < 4; mm++) {
                const int m = m4 * 4 + mm;
                ulonglong2 wA = *(const ulonglong2*)&W2s[m * 64 + kb1];
                ulonglong2 wB = *(const ulonglong2*)&W2s[m * 64 + kb2];
                unsigned long long hb;
                hb = packdup(h0[mm]);
                ffma2(acc[0][0], hb, wA.x); ffma2(acc[0][1], hb, wA.y);
                ffma2(acc[0][2], hb, wB.x); ffma2(acc[0][3], hb, wB.y);
                hb = packdup(h1[mm]);
                ffma2(acc[1][0], hb, wA.x); ffma2(acc[1][1], hb, wA.y);
                ffma2(acc[1][2], hb, wB.x); ffma2(acc[1][3], hb, wB.y);
                hb = packdup(h2[mm]);
                ffma2(acc[2][0], hb, wA.x); ffma2(acc[2][1], hb, wA.y);
                ffma2(acc[2][2], hb, wB.x); ffma2(acc[2][3], hb, wB.y);
                hb = packdup(h3[mm]);
                ffma2(acc[3][0], hb, wA.x); ffma2(acc[3][1], hb, wA.y);
                ffma2(acc[3][2], hb, wB.x); ffma2(acc[3][3], hb, wB.y);
            }
        }

        // ---- Prefetch next tile's idx (LDG latency hides under epilogue) --
        int nt = tile + gridDim.x;
        int pv = 0;
        bool doPref = (nt < nTiles);
        if (doPref) {
            int eg = nt * TILE_E + (tid & 63);
            if (tid < 64) pv = (eg < total) ? g_SRC[eg] : 0;
            else          pv = (eg < total) ? g_DST[eg] : -1;
        }

        // ---------------- Stage 3: scatter-max ----------------
#pragma unroll
        for (int i = 0; i < 4; i++) {
            int d = dbuf[e0 + 16 * i];
            if (d < 0) continue;
            float v0, v1, v2, v3, v4, v5, v6, v7;
            unpack2(acc[i][0], v0, v1);
            unpack2(acc[i][1], v2, v3);
            unpack2(acc[i][2], v4, v5);
            unpack2(acc[i][3], v6, v7);
            float* oA = out + d * 64 + kb1;
            float* oB = out + d * 64 + kb2;
            float4 curA = *(const float4*)oA;
            float4 curB = *(const float4*)oB;
            if (v0 > curA.x) atomicMaxF(oA + 0, v0);
            if (v1 > curA.y) atomicMaxF(oA + 1, v1);
            if (v2 > curA.z) atomicMaxF(oA + 2, v2);
            if (v3 > curA.w) atomicMaxF(oA + 3, v3);
            if (v4 > curB.x) atomicMaxF(oB + 0, v4);
            if (v5 > curB.y) atomicMaxF(oB + 1, v5);
            if (v6 > curB.z) atomicMaxF(oB + 2, v6);
            if (v7 > curB.w) atomicMaxF(oB + 3, v7);
        }

        // Store prefetched idx into the alternate buffer before the sync.
        if (doPref) ibuf[(b ^ 1) * 128 + tid] = pv;
        __syncthreads();   // Hs + ibuf handoff safe for next tile
    }
}

// ---------------------------------------------------------------------------
// Launch
// ---------------------------------------------------------------------------
extern "C" void kernel_launch(void* const* d_in, const int* in_sizes, int n_in,
                              void* d_out, int out_size) {
    const float* x   = (const float*)d_in[0];    // [n, 32]
    const float* pos = (const float*)d_in[1];    // [n, 3]
    const void*  ei  = d_in[2];                  // [2, E] int64 or int32
    const float* W1  = (const float*)d_in[3];    // [35, 64]
    const float* b1  = (const float*)d_in[4];    // [64]
    const float* W2  = (const float*)d_in[5];    // [64, 64]
    const float* b2  = (const float*)d_in[6];    // [64]
    float*       out = (float*)d_out;            // [n, 64]

    int n = in_sizes[0] / D_FEAT;
    int E = in_sizes[2] / 2;

    const int smemBytes = (TILE_E * H_STRIDE + 64 * 64 + 64) * 4 + 2 * 128 * 4;
    cudaFuncSetAttribute(edge_kernel, cudaFuncAttributeMaxDynamicSharedMemorySize,
                         smemBytes);

    // 1) fused setup: dtype detect + edge normalize + U/P precompute + init
    setup_kernel<<<1480, 256>>>(ei, x, pos, W1, b1, out, E, n);
    // 2) persistent edge kernel: 6 CTAs/SM x 148 SMs
    edge_kernel<<<888, 128, smemBytes>>>(W2, b2, out, n, E);
}